// round 6
// baseline (speedup 1.0000x reference)
#include <cuda_runtime.h>
#include <cuda_bf16.h>
#include <math.h>
#include <stdint.h>

#define BB 64
#define CC 64
#define NXX 128
#define NYY 128
#define SS (NXX*NYY)
#define MM2 12
#define KXN 24
#define NMODE (KXN*MM2)
#define NTT 50
#define LWSTRIDE (64*64*144)

#define APITCH 100   /* packed A pitch (words) */
#define BPITCH 136   /* packed B pitch */
#define OPITCH 132   /* packed output tile pitch */
#define B2PITCH 40   /* packed forward-basis pitch */

/* ------------ scratch ------------ */
__device__ unsigned g_xp[BB*CC*SS];          /* activations, packed bf16 hi/lo */
__device__ float  g_sparse[BB*SS];
__device__ float  g_counts[BB*SS];
__device__ float  g_grid[BB*SS];
__device__ float2 g_Ty[BB*CC*NXX*MM2];
__device__ float2 g_modes[BB*CC*NMODE];
__device__ float2 g_omodes[BB*CC*NMODE];
__device__ float2 g_U[BB*CC*NXX*MM2];
__device__ float2 g_Bx[KXN*NXX];
__device__ unsigned g_Bfwd[NYY*24];          /* packed fwd basis [y][col] col<12:cos col>=12:-sin */
__device__ unsigned g_Binv[32*NYY];          /* packed inv rows  [r][y]  r<12:cos 12-23:-sin 24:1 */

extern __shared__ float smf[];

__device__ __forceinline__ float gelu_f(float v){
    return 0.5f*v*(1.0f+erff(v*0.70710678118654752440f));
}
__device__ __forceinline__ unsigned packw(float v){
    __nv_bfloat16 h = __float2bfloat16_rn(v);
    float hf = __bfloat162float(h);
    __nv_bfloat16 l = __float2bfloat16_rn(v - hf);
    return (unsigned)__bfloat16_as_ushort(h) | ((unsigned)__bfloat16_as_ushort(l)<<16);
}
__device__ __forceinline__ float unpackw(unsigned w){
    return __bfloat162float(__ushort_as_bfloat16((unsigned short)(w&0xFFFFu)))
         + __bfloat162float(__ushort_as_bfloat16((unsigned short)(w>>16)));
}
__device__ __forceinline__ void mma_bf16(float c[4],
        unsigned a0,unsigned a1,unsigned a2,unsigned a3,
        unsigned b0,unsigned b1){
    asm("mma.sync.aligned.m16n8k16.row.col.f32.bf16.bf16.f32 "
        "{%0,%1,%2,%3}, {%4,%5,%6,%7}, {%8,%9}, {%0,%1,%2,%3};"
        : "+f"(c[0]),"+f"(c[1]),"+f"(c[2]),"+f"(c[3])
        : "r"(a0),"r"(a1),"r"(a2),"r"(a3),"r"(b0),"r"(b1));
}
/* full 3-product split: (a_hi+a_lo)(b_hi+b_lo) minus a_lo*b_lo */
__device__ __forceinline__ void mma2(float c[4],
        unsigned a0,unsigned a1,unsigned a2,unsigned a3,
        unsigned w0,unsigned w1){
    mma_bf16(c,a0,a1,a2,a3, __byte_perm(w0,0,0x1010), __byte_perm(w1,0,0x1010));
    mma_bf16(c,a0,a1,a2,a3, __byte_perm(w0,0,0x4432), __byte_perm(w1,0,0x4432));
}

/* ------------ basis tables ------------ */
__global__ void k_basis(){
    int t = threadIdx.x;
    for(int i=t;i<KXN*NXX;i+=blockDim.x){
        int kx=i>>7, x=i&127;
        int kg = kx<12 ? kx : kx+104;
        int m=(kg*x)&127;
        double a=(double)m*(6.283185307179586476925286766559/128.0);
        g_Bx[i]=make_float2((float)cos(a),(float)sin(a));
    }
    for(int i=t;i<NYY*24;i+=blockDim.x){
        int y=i/24, col=i-(i/24)*24;
        int ky = col<12 ? col : col-12;
        int m=(ky*y)&127;
        double a=(double)m*(6.283185307179586476925286766559/128.0);
        double v = (col<12)? cos(a) : -sin(a);
        g_Bfwd[i]=packw((float)v);
    }
    for(int i=t;i<32*NYY;i+=blockDim.x){
        int r=i>>7, y=i&127;
        float v;
        if(r<24){
            int ky = r<12 ? r : r-12;
            int m=(ky*y)&127;
            double a=(double)m*(6.283185307179586476925286766559/128.0);
            v = (r<12)? (float)cos(a) : (float)(-sin(a));
        } else v = (r==24)? 1.f : 0.f;
        g_Binv[i]=packw(v);
    }
}

/* ------------ sparse grid ------------ */
__global__ void k_zero(){
    int i = blockIdx.x*blockDim.x+threadIdx.x;
    if(i<BB*SS){ g_sparse[i]=0.f; g_counts[i]=0.f; }
}
__global__ void k_scatter(const float* __restrict__ xyt, const float* __restrict__ oc,
                          const float* __restrict__ ov, const int* __restrict__ nb,
                          const int* __restrict__ siy, const int* __restrict__ six){
    int b = threadIdx.x;
    if(b>=BB) return;
    float tq = xyt[b*3+2];
    float* sp = g_sparse + (size_t)b*SS;
    float* ct = g_counts + (size_t)b*SS;
    for(int k=0;k<64;k++){
        int idx = nb[b*64+k];
        int sid = idx / NTT;
        float tt = oc[idx*3+2];
        float w = expf(-0.1f*fabsf(tt-tq));
        float v = ov[idx]*w;
        int lin = siy[sid]*NYY + six[sid];
        sp[lin]+=v; ct[lin]+=w;
    }
}
__global__ void k_grid(){
    int i = blockIdx.x*blockDim.x+threadIdx.x;
    if(i<BB*SS){
        float c=g_counts[i];
        g_grid[i] = (c>0.f) ? g_sparse[i]/fmaxf(c,1e-6f) : 0.f;
    }
}

/* ------------ shared forward-y-DFT GEMM (bf16 split), M=64, N=24, K=128 ------ */
__device__ __forceinline__ void gemm_dfty(const unsigned* A, int ap, const unsigned* B2,
                                          int m0,int g,int t4,
                                          float* tbase, int tstride){
    float acc2[3][4];
    #pragma unroll
    for(int nt=0;nt<3;nt++){ acc2[nt][0]=0.f;acc2[nt][1]=0.f;acc2[nt][2]=0.f;acc2[nt][3]=0.f; }
    #pragma unroll 1
    for(int kk=0;kk<16;kk++){
        int kb=kk*8;
        unsigned a0=A[(m0+g)*ap+kb+t4];
        unsigned a1=A[(m0+8+g)*ap+kb+t4];
        unsigned a2=A[(m0+g)*ap+kb+4+t4];
        unsigned a3=A[(m0+8+g)*ap+kb+4+t4];
        #pragma unroll
        for(int nt=0;nt<3;nt++){
            unsigned w0=B2[(kb+t4)*B2PITCH + nt*8 + g];
            unsigned w1=B2[(kb+4+t4)*B2PITCH + nt*8 + g];
            mma2(acc2[nt],a0,a1,a2,a3,w0,w1);
        }
    }
    #pragma unroll
    for(int nt=0;nt<3;nt++){
        #pragma unroll
        for(int rr=0;rr<2;rr++){
            int o = m0 + rr*8 + g;
            float* Tf = tbase + (size_t)o*tstride;
            #pragma unroll
            for(int cc=0;cc<2;cc++){
                int col = nt*8 + 2*t4 + cc;
                int ky = (col<12)? col : col-12;
                int im = (col<12)? 0 : 1;
                Tf[ky*2+im] = acc2[nt][rr*2+cc];
            }
        }
    }
}

/* ------------ k01: fused fc0 (rank-3 outer product) + pack + forward y-DFT ---- */
__global__ void __launch_bounds__(256) k01(const float* __restrict__ xg, const float* __restrict__ yg,
                                           const float* __restrict__ w, const float* __restrict__ bias){
    unsigned* sOp = (unsigned*)smf;             /* 64*OPITCH = 8448 */
    unsigned* sB2 = sOp + 64*OPITCH;            /* 128*B2PITCH = 5120 */
    float* aux = (float*)(sB2 + 128*B2PITCH);
    float* gl=aux; float* xl=aux+128; float* yl=aux+256;
    float* w0=aux+384; float* w1=w0+64; float* w2=w1+64; float* bs=w2+64;

    int b = blockIdx.x>>7, x = blockIdx.x&127;
    int tid = threadIdx.x;

    for(int i=tid;i<128;i+=256){
        gl[i]=g_grid[(size_t)b*SS + x*128 + i];
        xl[i]=xg[x*128+i];
        yl[i]=yg[x*128+i];
    }
    for(int i=tid;i<64;i+=256){ w0[i]=w[i]; w1[i]=w[64+i]; w2[i]=w[128+i]; bs[i]=bias[i]; }
    for(int i=tid;i<NYY*24;i+=256){
        int y=i/24, col=i-(i/24)*24;
        sB2[y*B2PITCH+col]=g_Bfwd[i];
    }
    __syncthreads();
    for(int i=tid;i<8192;i+=256){
        int c=i>>7, y=i&127;
        float v = gl[y]*w0[c] + xl[y]*w1[c] + yl[y]*w2[c] + bs[c];
        unsigned pv = packw(v);
        sOp[c*OPITCH+y]=pv;
        g_xp[((size_t)(b*64+c)*128+x)*128 + y] = pv;
    }
    __syncthreads();
    int lane=tid&31, wd=tid>>5;
    if(wd<4){
        gemm_dfty(sOp, OPITCH, sB2, wd*16, lane>>2, lane&3,
                  (float*)g_Ty + ((size_t)b*8192 + x)*24, 3072);
    }
}

/* ------------ K2: DFT along x at 24 modes ------------ */
__global__ void k2_dftx(){
    __shared__ float2 sT[128*12];
    __shared__ float2 sb[24*129];
    int bc = blockIdx.x;
    const float2* tp = g_Ty + (size_t)bc*1536;
    for(int i=threadIdx.x;i<1536;i+=288) sT[i]=tp[i];
    for(int i=threadIdx.x;i<24*128;i+=288){ int kx=i>>7,x=i&127; sb[kx*129+x]=g_Bx[i]; }
    __syncthreads();
    int kx = threadIdx.x/12;
    int ky = threadIdx.x - kx*12;
    float are=0.f, aim=0.f;
    #pragma unroll 4
    for(int x=0;x<128;x++){
        float2 t = sT[x*12+ky];
        float2 e = sb[kx*129+x];
        are += t.x*e.x + t.y*e.y;
        aim += t.y*e.x - t.x*e.y;
    }
    g_modes[(size_t)bc*NMODE + kx*12 + ky] = make_float2(are,aim);
}

/* ------------ K3: per-mode complex 64x64 mix ------------ */
__global__ void k3_specmul(const float* __restrict__ w1r, const float* __restrict__ w1i,
                           const float* __restrict__ w2r, const float* __restrict__ w2i){
    __shared__ float2 sW[4096];
    __shared__ float2 sM[2048];
    int m  = blockIdx.x>>1;
    int bh = blockIdx.x&1;
    int kx = m/12, ky = m - kx*12;
    const float *wr, *wi; int kxw;
    if(kx<12){ wr=w1r; wi=w1i; kxw=kx; } else { wr=w2r; wi=w2i; kxw=kx-12; }
    int wofs = kxw*12+ky;
    for(int i=threadIdx.x;i<4096;i+=256)
        sW[i] = make_float2(wr[i*144+wofs], wi[i*144+wofs]);
    for(int i=threadIdx.x;i<2048;i+=256){
        int bl=i>>6, c=i&63;
        sM[i] = g_modes[((size_t)((bh*32+bl)*64+c))*NMODE + m];
    }
    __syncthreads();
    for(int k=0;k<8;k++){
        int idx = threadIdx.x + k*256;
        int bl = idx>>6, o = idx&63;
        float are=0.f, aim=0.f;
        #pragma unroll 4
        for(int i=0;i<64;i++){
            float2 mv=sM[bl*64+i];
            float2 wv=sW[i*64+o];
            are += mv.x*wv.x - mv.y*wv.y;
            aim += mv.x*wv.y + mv.y*wv.x;
        }
        g_omodes[((size_t)((bh*32+bl)*64+o))*NMODE + m] = make_float2(are,aim);
    }
}

/* ------------ K4: inverse DFT along x ------------ */
__global__ void k4_invx(){
    __shared__ float2 sO[288];
    __shared__ float2 sb[24*129];
    int bc = blockIdx.x;
    const float2* op = g_omodes + (size_t)bc*NMODE;
    for(int i=threadIdx.x;i<288;i+=384) sO[i]=op[i];
    for(int i=threadIdx.x;i<24*128;i+=384){ int kx=i>>7,x=i&127; sb[kx*129+x]=g_Bx[i]; }
    __syncthreads();
    int xb = threadIdx.x/12;
    int ky = threadIdx.x - xb*12;
    float scale = (ky==0 ? 1.f : 2.f)*(1.f/16384.f);
    for(int j=0;j<4;j++){
        int x = xb + 32*j;
        float are=0.f, aim=0.f;
        #pragma unroll
        for(int kx=0;kx<24;kx++){
            float2 o = sO[kx*12+ky];
            float2 e = sb[kx*129+x];
            are += o.x*e.x - o.y*e.y;
            aim += o.x*e.y + o.y*e.x;
        }
        g_U[((size_t)bc*128+x)*12+ky] = make_float2(are*scale, aim*scale);
    }
}

/* ------------ K5: fused GEMM (W@X + inv-y + bias, K=96) + GELU + fwd y-DFT ---- */
__global__ void __launch_bounds__(256) k5_mma(const float* __restrict__ pw,
                                              const float* __restrict__ pwb){
    unsigned* sAp = (unsigned*)smf;             /* 64*APITCH  = 6400  */
    unsigned* sBp = sAp + 64*APITCH;            /* 96*BPITCH  = 13056 */
    unsigned* sB2 = sBp + 96*BPITCH;            /* 128*B2PITCH= 5120  */
    unsigned* sOp = sB2 + 128*B2PITCH;          /* 64*OPITCH  = 8448  */

    int b = blockIdx.x >> 7;
    int x = blockIdx.x & 127;
    int tid = threadIdx.x;

    /* A: k<64 = W[o][c]; 64..75 Ure; 76..87 Uim; 88 bias; 89..95 zero */
    for(int i=tid;i<4096;i+=256) sAp[(i>>6)*APITCH + (i&63)] = packw(pw[i]);
    for(int i=tid;i<768;i+=256){
        int o=i/12, ky=i-(i/12)*12;
        float2 u = g_U[(((size_t)(b*64+o))*128+x)*12+ky];
        sAp[o*APITCH + 64 + ky] = packw(u.x);
        sAp[o*APITCH + 76 + ky] = packw(u.y);
    }
    for(int i=tid;i<512;i+=256){
        int o=i>>3, j=i&7;
        sAp[o*APITCH + 88 + j] = (j==0)? packw(pwb[o]) : 0u;
    }
    /* B rows 0..63 = packed X (straight copy) */
    for(int i=tid;i<2048;i+=256){
        int c=i>>5, yq=i&31;
        uint4 v = ((const uint4*)(g_xp + (((size_t)(b*64+c)*128+x)<<7)))[yq];
        *(uint4*)(sBp + c*BPITCH + yq*4) = v;
    }
    /* B rows 64..95 = packed inverse basis */
    for(int i=tid;i<4096;i+=256){
        int r=i>>7, y=i&127;
        sBp[(64+r)*BPITCH + y] = g_Binv[i];
    }
    /* forward basis */
    for(int i=tid;i<NYY*24;i+=256){
        int y=i/24, col=i-(i/24)*24;
        sB2[y*B2PITCH+col]=g_Bfwd[i];
    }
    __syncthreads();

    int lane = tid&31, wd = tid>>5;
    int m0 = (wd&3)*16, n0 = (wd>>2)*64;
    int g = lane>>2, t4 = lane&3;

    float acc[8][4];
    #pragma unroll
    for(int nt=0;nt<8;nt++){ acc[nt][0]=0.f;acc[nt][1]=0.f;acc[nt][2]=0.f;acc[nt][3]=0.f; }

    #pragma unroll 1
    for(int kk=0;kk<12;kk++){
        int kb = kk*8;
        unsigned a0=sAp[(m0+g)*APITCH + kb + t4];
        unsigned a1=sAp[(m0+8+g)*APITCH + kb + t4];
        unsigned a2=sAp[(m0+g)*APITCH + kb + 4 + t4];
        unsigned a3=sAp[(m0+8+g)*APITCH + kb + 4 + t4];
        #pragma unroll
        for(int nt=0;nt<8;nt++){
            unsigned w0 = sBp[(kb+t4)*BPITCH + n0 + nt*8 + g];
            unsigned w1 = sBp[(kb+4+t4)*BPITCH + n0 + nt*8 + g];
            mma2(acc[nt],a0,a1,a2,a3,w0,w1);
        }
    }

    /* GELU + pack -> sOp */
    #pragma unroll
    for(int nt=0;nt<8;nt++){
        int y0 = n0 + nt*8 + 2*t4;
        sOp[(m0+g)*OPITCH + y0]     = packw(gelu_f(acc[nt][0]));
        sOp[(m0+g)*OPITCH + y0+1]   = packw(gelu_f(acc[nt][1]));
        sOp[(m0+8+g)*OPITCH + y0]   = packw(gelu_f(acc[nt][2]));
        sOp[(m0+8+g)*OPITCH + y0+1] = packw(gelu_f(acc[nt][3]));
    }
    __syncthreads();

    if(wd>=4){
        /* warps 4-7: coalesced store of packed x for next layer / final */
        for(int i=tid-128;i<2048;i+=128){
            int c=i>>5, yq=i&31;
            uint4 v = *(const uint4*)(sOp + c*OPITCH + yq*4);
            ((uint4*)(g_xp + (((size_t)(b*64+c)*128+x)<<7)))[yq]=v;
        }
    } else {
        /* warps 0-3: fused next-layer forward y-DFT */
        gemm_dfty(sOp, OPITCH, sB2, m0, g, t4,
                  (float*)g_Ty + ((size_t)b*8192 + x)*24, 3072);
    }
}

/* ------------ final ------------ */
__global__ void k_final(const float* __restrict__ xyt,
                        const float* __restrict__ pw, const float* __restrict__ pwb,
                        const float* __restrict__ fc1w, const float* __restrict__ fc1b,
                        const float* __restrict__ fc2w, const float* __restrict__ fc2b,
                        const int* __restrict__ Lxp, const int* __restrict__ Lyp,
                        float* __restrict__ out){
    __shared__ float  sXv[64];
    __shared__ float2 sPh[288];
    __shared__ float  sPart[128];
    __shared__ float  sY3[64];
    __shared__ float  sH[128];
    int b = blockIdx.x;
    int t = threadIdx.x;

    int rlx = Lxp[0], rly = Lyp[0];
    float Lx = (rlx>0 && rlx<(1<<23)) ? (float)rlx : __int_as_float(rlx);
    float Ly = (rly>0 && rly<(1<<23)) ? (float)rly : __int_as_float(rly);
    float qx = xyt[b*3+0], qy = xyt[b*3+1];
    float x01 = fminf(fmaxf(qx/fmaxf(Lx,1e-6f),0.f),1.f);
    float y01 = fminf(fmaxf(qy/fmaxf(Ly,1e-6f),0.f),1.f);
    float gx = x01*127.f, gy = y01*127.f;
    int x0 = (int)floorf(gx), y0 = (int)floorf(gy);
    int x1 = min(x0+1,127),  y1 = min(y0+1,127);
    float wx = gx-(float)x0, wy = gy-(float)y0;

    float outAcc = 0.f;

    for(int p=0;p<4;p++){
        int ix = p&1, iy = p>>1;
        int px = ix? x1:x0;
        int py = iy? y1:y0;
        float wgt = (ix? wx : 1.f-wx)*(iy? wy : 1.f-wy);

        for(int m=t;m<288;m+=128){
            int kx=m/12, ky=m-kx*12;
            int kg = kx<12 ? kx : kx+104;
            int mm = (kg*px + ky*py)&127;
            float a = (float)mm*(6.2831853071795864769f/128.f);
            float sv,cv; sincosf(a,&sv,&cv);
            float sc = (ky==0?1.f:2.f)*(1.f/16384.f);
            sPh[m] = make_float2(cv*sc, sv*sc);
        }
        if(t<64) sXv[t] = unpackw(g_xp[((((size_t)(b*64+t))*128+px)<<7)+py]);
        __syncthreads();
        {
            int o = t&63, h = t>>6;
            const float2* op = g_omodes + (size_t)(b*64+o)*288 + h*144;
            const float2* ph = sPh + h*144;
            float acc=0.f;
            #pragma unroll 4
            for(int m=0;m<144;m++){
                float2 z=op[m]; float2 e=ph[m];
                acc += z.x*e.x - z.y*e.y;
            }
            sPart[t]=acc;
        }
        __syncthreads();
        if(t<64){
            float v = sPart[t]+sPart[t+64];
            float a = pwb[t];
            #pragma unroll 4
            for(int c=0;c<64;c++) a += sXv[c]*pw[t*64+c];
            sY3[t] = v + a;
        }
        __syncthreads();
        {
            float a = fc1b[t];
            #pragma unroll 4
            for(int o=0;o<64;o++) a += sY3[o]*fc1w[o*128+t];
            sH[t] = gelu_f(a);
        }
        __syncthreads();
        if(t<3){
            float a = fc2b[t];
            #pragma unroll 4
            for(int f=0;f<128;f++) a += sH[f]*fc2w[f*3+t];
            outAcc += wgt*a;
        }
        __syncthreads();
    }
    if(t<3) out[b*3+t]=outAcc;
}

/* ------------ launch ------------ */
extern "C" void kernel_launch(void* const* d_in, const int* in_sizes, int n_in,
                              void* d_out, int out_size){
    const float* xyt   = (const float*)d_in[0];
    const float* oc    = (const float*)d_in[1];
    const float* ov    = (const float*)d_in[2];
    const float* xg    = (const float*)d_in[3];
    const float* yg    = (const float*)d_in[4];
    const float* fc0w  = (const float*)d_in[5];
    const float* fc0b  = (const float*)d_in[6];
    const float* w1r   = (const float*)d_in[7];
    const float* w1i   = (const float*)d_in[8];
    const float* w2r   = (const float*)d_in[9];
    const float* w2i   = (const float*)d_in[10];
    const float* pww   = (const float*)d_in[11];
    const float* pwb   = (const float*)d_in[12];
    const float* fc1w  = (const float*)d_in[13];
    const float* fc1b  = (const float*)d_in[14];
    const float* fc2w  = (const float*)d_in[15];
    const float* fc2b  = (const float*)d_in[16];
    const int*   nb    = (const int*)d_in[17];
    const int*   siy   = (const int*)d_in[18];
    const int*   six   = (const int*)d_in[19];
    const int*   Lxp   = (const int*)d_in[20];
    const int*   Lyp   = (const int*)d_in[21];
    float* out = (float*)d_out;

    const int SM01 = (64*OPITCH + 128*B2PITCH + 640)*4;
    const int SM5  = (64*APITCH + 96*BPITCH + 128*B2PITCH + 64*OPITCH)*4;
    cudaFuncSetAttribute(k01,    cudaFuncAttributeMaxDynamicSharedMemorySize, SM01);
    cudaFuncSetAttribute(k5_mma, cudaFuncAttributeMaxDynamicSharedMemorySize, SM5);

    k_basis<<<1,256>>>();
    k_zero<<<(BB*SS)/256,256>>>();
    k_scatter<<<1,64>>>(xyt,oc,ov,nb,siy,six);
    k_grid<<<(BB*SS)/256,256>>>();

    k01<<<BB*NXX,256,SM01>>>(xg,yg,fc0w,fc0b);

    for(int L=0;L<4;L++){
        k2_dftx<<<BB*CC,288>>>();
        k3_specmul<<<NMODE*2,256>>>(w1r+(size_t)L*LWSTRIDE, w1i+(size_t)L*LWSTRIDE,
                                    w2r+(size_t)L*LWSTRIDE, w2i+(size_t)L*LWSTRIDE);
        if(L<3){
            k4_invx<<<BB*CC,384>>>();
            k5_mma<<<BB*NXX,256,SM5>>>(pww+(size_t)L*4096, pwb+(size_t)L*64);
        }
    }
    k_final<<<BB,128>>>(xyt, pww+3*4096, pwb+3*64,
                        fc1w, fc1b, fc2w, fc2b, Lxp, Lyp, out);
}

// round 8
// speedup vs baseline: 1.0083x; 1.0083x over previous
#include <cuda_runtime.h>
#include <cuda_bf16.h>
#include <math.h>
#include <stdint.h>

#define BB 64
#define CC 64
#define NXX 128
#define NYY 128
#define SS (NXX*NYY)
#define MM2 12
#define KXN 24
#define NMODE (KXN*MM2)
#define NTT 50
#define LWSTRIDE (64*64*144)

#define APITCH 100   /* packed A pitch (words) */
#define BPITCH 136   /* packed B pitch */
#define OPITCH 132   /* packed output tile pitch */
#define B2PITCH 40   /* packed forward-basis pitch */

/* ------------ scratch ------------ */
__device__ unsigned g_xp[BB*CC*SS];          /* activations, packed bf16 hi/lo */
__device__ float  g_sparse[BB*SS];
__device__ float  g_counts[BB*SS];
__device__ float  g_grid[BB*SS];
__device__ float2 g_Ty[BB*CC*NXX*MM2];
__device__ float2 g_modes[BB*CC*NMODE];
__device__ float2 g_omodes[BB*CC*NMODE];
__device__ float2 g_U[BB*CC*NXX*MM2];
__device__ float2 g_Bx[KXN*NXX];
__device__ unsigned g_Bfwd[NYY*24];          /* packed fwd basis [y][col] col<12:cos col>=12:-sin */
__device__ unsigned g_Binv[32*NYY];          /* packed inv rows  [r][y]  r<12:cos 12-23:-sin 24:1 */

extern __shared__ float smf[];

__device__ __forceinline__ float gelu_f(float v){
    return 0.5f*v*(1.0f+erff(v*0.70710678118654752440f));
}
__device__ __forceinline__ unsigned packw(float v){
    __nv_bfloat16 h = __float2bfloat16_rn(v);
    float hf = __bfloat162float(h);
    __nv_bfloat16 l = __float2bfloat16_rn(v - hf);
    return (unsigned)__bfloat16_as_ushort(h) | ((unsigned)__bfloat16_as_ushort(l)<<16);
}
__device__ __forceinline__ float unpackw(unsigned w){
    return __bfloat162float(__ushort_as_bfloat16((unsigned short)(w&0xFFFFu)))
         + __bfloat162float(__ushort_as_bfloat16((unsigned short)(w>>16)));
}
__device__ __forceinline__ void mma_bf16(float c[4],
        unsigned a0,unsigned a1,unsigned a2,unsigned a3,
        unsigned b0,unsigned b1){
    asm("mma.sync.aligned.m16n8k16.row.col.f32.bf16.bf16.f32 "
        "{%0,%1,%2,%3}, {%4,%5,%6,%7}, {%8,%9}, {%0,%1,%2,%3};"
        : "+f"(c[0]),"+f"(c[1]),"+f"(c[2]),"+f"(c[3])
        : "r"(a0),"r"(a1),"r"(a2),"r"(a3),"r"(b0),"r"(b1));
}
/* full 3-product split: (a_hi+a_lo)(b_hi+b_lo) minus a_lo*b_lo */
__device__ __forceinline__ void mma2(float c[4],
        unsigned a0,unsigned a1,unsigned a2,unsigned a3,
        unsigned w0,unsigned w1){
    mma_bf16(c,a0,a1,a2,a3, __byte_perm(w0,0,0x1010), __byte_perm(w1,0,0x1010));
    mma_bf16(c,a0,a1,a2,a3, __byte_perm(w0,0,0x4432), __byte_perm(w1,0,0x4432));
}

/* ------------ basis tables ------------ */
__global__ void k_basis(){
    int t = threadIdx.x;
    for(int i=t;i<KXN*NXX;i+=blockDim.x){
        int kx=i>>7, x=i&127;
        int kg = kx<12 ? kx : kx+104;
        int m=(kg*x)&127;
        double a=(double)m*(6.283185307179586476925286766559/128.0);
        g_Bx[i]=make_float2((float)cos(a),(float)sin(a));
    }
    for(int i=t;i<NYY*24;i+=blockDim.x){
        int y=i/24, col=i-(i/24)*24;
        int ky = col<12 ? col : col-12;
        int m=(ky*y)&127;
        double a=(double)m*(6.283185307179586476925286766559/128.0);
        double v = (col<12)? cos(a) : -sin(a);
        g_Bfwd[i]=packw((float)v);
    }
    for(int i=t;i<32*NYY;i+=blockDim.x){
        int r=i>>7, y=i&127;
        float v;
        if(r<24){
            int ky = r<12 ? r : r-12;
            int m=(ky*y)&127;
            double a=(double)m*(6.283185307179586476925286766559/128.0);
            v = (r<12)? (float)cos(a) : (float)(-sin(a));
        } else v = (r==24)? 1.f : 0.f;
        g_Binv[i]=packw(v);
    }
}

/* ------------ sparse grid ------------ */
__global__ void k_zero(){
    int i = blockIdx.x*blockDim.x+threadIdx.x;
    if(i<BB*SS){ g_sparse[i]=0.f; g_counts[i]=0.f; }
}
__global__ void k_scatter(const float* __restrict__ xyt, const float* __restrict__ oc,
                          const float* __restrict__ ov, const int* __restrict__ nb,
                          const int* __restrict__ siy, const int* __restrict__ six){
    int b = threadIdx.x;
    if(b>=BB) return;
    float tq = xyt[b*3+2];
    float* sp = g_sparse + (size_t)b*SS;
    float* ct = g_counts + (size_t)b*SS;
    for(int k=0;k<64;k++){
        int idx = nb[b*64+k];
        int sid = idx / NTT;
        float tt = oc[idx*3+2];
        float w = expf(-0.1f*fabsf(tt-tq));
        float v = ov[idx]*w;
        int lin = siy[sid]*NYY + six[sid];
        sp[lin]+=v; ct[lin]+=w;
    }
}
__global__ void k_grid(){
    int i = blockIdx.x*blockDim.x+threadIdx.x;
    if(i<BB*SS){
        float c=g_counts[i];
        g_grid[i] = (c>0.f) ? g_sparse[i]/fmaxf(c,1e-6f) : 0.f;
    }
}

/* ------------ shared forward-y-DFT GEMM (bf16 split), M=64, N=24, K=128 ------ */
__device__ __forceinline__ void gemm_dfty(const unsigned* A, int ap, const unsigned* B2,
                                          int m0,int g,int t4,
                                          float* tbase, int tstride){
    float acc2[3][4];
    #pragma unroll
    for(int nt=0;nt<3;nt++){ acc2[nt][0]=0.f;acc2[nt][1]=0.f;acc2[nt][2]=0.f;acc2[nt][3]=0.f; }
    #pragma unroll 1
    for(int kk=0;kk<16;kk++){
        int kb=kk*8;
        unsigned a0=A[(m0+g)*ap+kb+t4];
        unsigned a1=A[(m0+8+g)*ap+kb+t4];
        unsigned a2=A[(m0+g)*ap+kb+4+t4];
        unsigned a3=A[(m0+8+g)*ap+kb+4+t4];
        #pragma unroll
        for(int nt=0;nt<3;nt++){
            unsigned w0=B2[(kb+t4)*B2PITCH + nt*8 + g];
            unsigned w1=B2[(kb+4+t4)*B2PITCH + nt*8 + g];
            mma2(acc2[nt],a0,a1,a2,a3,w0,w1);
        }
    }
    #pragma unroll
    for(int nt=0;nt<3;nt++){
        #pragma unroll
        for(int rr=0;rr<2;rr++){
            int o = m0 + rr*8 + g;
            float* Tf = tbase + (size_t)o*tstride;
            #pragma unroll
            for(int cc=0;cc<2;cc++){
                int col = nt*8 + 2*t4 + cc;
                int ky = (col<12)? col : col-12;
                int im = (col<12)? 0 : 1;
                Tf[ky*2+im] = acc2[nt][rr*2+cc];
            }
        }
    }
}

/* ------------ k01: fused fc0 (rank-3 outer product) + pack + forward y-DFT ---- */
__global__ void __launch_bounds__(256) k01(const float* __restrict__ xg, const float* __restrict__ yg,
                                           const float* __restrict__ w, const float* __restrict__ bias){
    unsigned* sOp = (unsigned*)smf;             /* 64*OPITCH = 8448 */
    unsigned* sB2 = sOp + 64*OPITCH;            /* 128*B2PITCH = 5120 */
    float* aux = (float*)(sB2 + 128*B2PITCH);
    float* gl=aux; float* xl=aux+128; float* yl=aux+256;
    float* w0=aux+384; float* w1=w0+64; float* w2=w1+64; float* bs=w2+64;

    int b = blockIdx.x>>7, x = blockIdx.x&127;
    int tid = threadIdx.x;

    for(int i=tid;i<128;i+=256){
        gl[i]=g_grid[(size_t)b*SS + x*128 + i];
        xl[i]=xg[x*128+i];
        yl[i]=yg[x*128+i];
    }
    for(int i=tid;i<64;i+=256){ w0[i]=w[i]; w1[i]=w[64+i]; w2[i]=w[128+i]; bs[i]=bias[i]; }
    for(int i=tid;i<NYY*24;i+=256){
        int y=i/24, col=i-(i/24)*24;
        sB2[y*B2PITCH+col]=g_Bfwd[i];
    }
    __syncthreads();
    for(int i=tid;i<8192;i+=256){
        int c=i>>7, y=i&127;
        float v = gl[y]*w0[c] + xl[y]*w1[c] + yl[y]*w2[c] + bs[c];
        unsigned pv = packw(v);
        sOp[c*OPITCH+y]=pv;
        g_xp[((size_t)(b*64+c)*128+x)*128 + y] = pv;
    }
    __syncthreads();
    int lane=tid&31, wd=tid>>5;
    if(wd<4){
        gemm_dfty(sOp, OPITCH, sB2, wd*16, lane>>2, lane&3,
                  (float*)g_Ty + ((size_t)b*8192 + x)*24, 3072);
    }
}

/* ------------ K2: DFT along x at 24 modes ------------ */
__global__ void k2_dftx(){
    __shared__ float2 sT[128*12];
    __shared__ float2 sb[24*129];
    int bc = blockIdx.x;
    const float2* tp = g_Ty + (size_t)bc*1536;
    for(int i=threadIdx.x;i<1536;i+=288) sT[i]=tp[i];
    for(int i=threadIdx.x;i<24*128;i+=288){ int kx=i>>7,x=i&127; sb[kx*129+x]=g_Bx[i]; }
    __syncthreads();
    int kx = threadIdx.x/12;
    int ky = threadIdx.x - kx*12;
    float are=0.f, aim=0.f;
    #pragma unroll 4
    for(int x=0;x<128;x++){
        float2 t = sT[x*12+ky];
        float2 e = sb[kx*129+x];
        are += t.x*e.x + t.y*e.y;
        aim += t.y*e.x - t.x*e.y;
    }
    g_modes[(size_t)bc*NMODE + kx*12 + ky] = make_float2(are,aim);
}

/* ------------ K3: per-mode complex 64x64 mix ------------ */
__global__ void k3_specmul(const float* __restrict__ w1r, const float* __restrict__ w1i,
                           const float* __restrict__ w2r, const float* __restrict__ w2i){
    __shared__ float2 sW[4096];
    __shared__ float2 sM[2048];
    int m  = blockIdx.x>>1;
    int bh = blockIdx.x&1;
    int kx = m/12, ky = m - kx*12;
    const float *wr, *wi; int kxw;
    if(kx<12){ wr=w1r; wi=w1i; kxw=kx; } else { wr=w2r; wi=w2i; kxw=kx-12; }
    int wofs = kxw*12+ky;
    for(int i=threadIdx.x;i<4096;i+=256)
        sW[i] = make_float2(wr[i*144+wofs], wi[i*144+wofs]);
    for(int i=threadIdx.x;i<2048;i+=256){
        int bl=i>>6, c=i&63;
        sM[i] = g_modes[((size_t)((bh*32+bl)*64+c))*NMODE + m];
    }
    __syncthreads();
    for(int k=0;k<8;k++){
        int idx = threadIdx.x + k*256;
        int bl = idx>>6, o = idx&63;
        float are=0.f, aim=0.f;
        #pragma unroll 4
        for(int i=0;i<64;i++){
            float2 mv=sM[bl*64+i];
            float2 wv=sW[i*64+o];
            are += mv.x*wv.x - mv.y*wv.y;
            aim += mv.x*wv.y + mv.y*wv.x;
        }
        g_omodes[((size_t)((bh*32+bl)*64+o))*NMODE + m] = make_float2(are,aim);
    }
}

/* ------------ K4: inverse DFT along x ------------ */
__global__ void k4_invx(){
    __shared__ float2 sO[288];
    __shared__ float2 sb[24*129];
    int bc = blockIdx.x;
    const float2* op = g_omodes + (size_t)bc*NMODE;
    for(int i=threadIdx.x;i<288;i+=384) sO[i]=op[i];
    for(int i=threadIdx.x;i<24*128;i+=384){ int kx=i>>7,x=i&127; sb[kx*129+x]=g_Bx[i]; }
    __syncthreads();
    int xb = threadIdx.x/12;
    int ky = threadIdx.x - xb*12;
    float scale = (ky==0 ? 1.f : 2.f)*(1.f/16384.f);
    for(int j=0;j<4;j++){
        int x = xb + 32*j;
        float are=0.f, aim=0.f;
        #pragma unroll
        for(int kx=0;kx<24;kx++){
            float2 o = sO[kx*12+ky];
            float2 e = sb[kx*129+x];
            are += o.x*e.x - o.y*e.y;
            aim += o.x*e.y + o.y*e.x;
        }
        g_U[((size_t)bc*128+x)*12+ky] = make_float2(are*scale, aim*scale);
    }
}

/* ------------ K5: fused GEMM (W@X + inv-y + bias, K=96) + GELU + fwd y-DFT ---- */
__global__ void __launch_bounds__(256) k5_mma(const float* __restrict__ pw,
                                              const float* __restrict__ pwb){
    unsigned* sAp = (unsigned*)smf;             /* 64*APITCH  = 6400  */
    unsigned* sBp = sAp + 64*APITCH;            /* 96*BPITCH  = 13056 */
    unsigned* sB2 = sBp + 96*BPITCH;            /* 128*B2PITCH= 5120  */
    unsigned* sOp = sB2 + 128*B2PITCH;          /* 64*OPITCH  = 8448  */

    int b = blockIdx.x >> 7;
    int x = blockIdx.x & 127;
    int tid = threadIdx.x;

    /* A: k<64 = W[o][c]; 64..75 Ure; 76..87 Uim; 88 bias; 89..95 zero */
    for(int i=tid;i<4096;i+=256) sAp[(i>>6)*APITCH + (i&63)] = packw(pw[i]);
    for(int i=tid;i<768;i+=256){
        int o=i/12, ky=i-(i/12)*12;
        float2 u = g_U[(((size_t)(b*64+o))*128+x)*12+ky];
        sAp[o*APITCH + 64 + ky] = packw(u.x);
        sAp[o*APITCH + 76 + ky] = packw(u.y);
    }
    for(int i=tid;i<512;i+=256){
        int o=i>>3, j=i&7;
        sAp[o*APITCH + 88 + j] = (j==0)? packw(pwb[o]) : 0u;
    }
    /* B rows 0..63 = packed X (straight copy) */
    for(int i=tid;i<2048;i+=256){
        int c=i>>5, yq=i&31;
        uint4 v = ((const uint4*)(g_xp + (((size_t)(b*64+c)*128+x)<<7)))[yq];
        *(uint4*)(sBp + c*BPITCH + yq*4) = v;
    }
    /* B rows 64..95 = packed inverse basis */
    for(int i=tid;i<4096;i+=256){
        int r=i>>7, y=i&127;
        sBp[(64+r)*BPITCH + y] = g_Binv[i];
    }
    /* forward basis */
    for(int i=tid;i<NYY*24;i+=256){
        int y=i/24, col=i-(i/24)*24;
        sB2[y*B2PITCH+col]=g_Bfwd[i];
    }
    __syncthreads();

    int lane = tid&31, wd = tid>>5;
    int m0 = (wd&3)*16, n0 = (wd>>2)*64;
    int g = lane>>2, t4 = lane&3;

    float acc[8][4];
    #pragma unroll
    for(int nt=0;nt<8;nt++){ acc[nt][0]=0.f;acc[nt][1]=0.f;acc[nt][2]=0.f;acc[nt][3]=0.f; }

    #pragma unroll 1
    for(int kk=0;kk<12;kk++){
        int kb = kk*8;
        unsigned a0=sAp[(m0+g)*APITCH + kb + t4];
        unsigned a1=sAp[(m0+8+g)*APITCH + kb + t4];
        unsigned a2=sAp[(m0+g)*APITCH + kb + 4 + t4];
        unsigned a3=sAp[(m0+8+g)*APITCH + kb + 4 + t4];
        #pragma unroll
        for(int nt=0;nt<8;nt++){
            unsigned w0 = sBp[(kb+t4)*BPITCH + n0 + nt*8 + g];
            unsigned w1 = sBp[(kb+4+t4)*BPITCH + n0 + nt*8 + g];
            mma2(acc[nt],a0,a1,a2,a3,w0,w1);
        }
    }

    /* GELU + pack -> sOp */
    #pragma unroll
    for(int nt=0;nt<8;nt++){
        int y0 = n0 + nt*8 + 2*t4;
        sOp[(m0+g)*OPITCH + y0]     = packw(gelu_f(acc[nt][0]));
        sOp[(m0+g)*OPITCH + y0+1]   = packw(gelu_f(acc[nt][1]));
        sOp[(m0+8+g)*OPITCH + y0]   = packw(gelu_f(acc[nt][2]));
        sOp[(m0+8+g)*OPITCH + y0+1] = packw(gelu_f(acc[nt][3]));
    }
    __syncthreads();

    if(wd>=4){
        /* warps 4-7: coalesced store of packed x for next layer / final */
        for(int i=tid-128;i<2048;i+=128){
            int c=i>>5, yq=i&31;
            uint4 v = *(const uint4*)(sOp + c*OPITCH + yq*4);
            ((uint4*)(g_xp + (((size_t)(b*64+c)*128+x)<<7)))[yq]=v;
        }
    } else {
        /* warps 0-3: fused next-layer forward y-DFT */
        gemm_dfty(sOp, OPITCH, sB2, m0, g, t4,
                  (float*)g_Ty + ((size_t)b*8192 + x)*24, 3072);
    }
}

/* ------------ final ------------ */
__global__ void k_final(const float* __restrict__ xyt,
                        const float* __restrict__ pw, const float* __restrict__ pwb,
                        const float* __restrict__ fc1w, const float* __restrict__ fc1b,
                        const float* __restrict__ fc2w, const float* __restrict__ fc2b,
                        const int* __restrict__ Lxp, const int* __restrict__ Lyp,
                        float* __restrict__ out){
    __shared__ float  sXv[64];
    __shared__ float2 sPh[288];
    __shared__ float  sPart[128];
    __shared__ float  sY3[64];
    __shared__ float  sH[128];
    int b = blockIdx.x;
    int t = threadIdx.x;

    int rlx = Lxp[0], rly = Lyp[0];
    float Lx = (rlx>0 && rlx<(1<<23)) ? (float)rlx : __int_as_float(rlx);
    float Ly = (rly>0 && rly<(1<<23)) ? (float)rly : __int_as_float(rly);
    float qx = xyt[b*3+0], qy = xyt[b*3+1];
    float x01 = fminf(fmaxf(qx/fmaxf(Lx,1e-6f),0.f),1.f);
    float y01 = fminf(fmaxf(qy/fmaxf(Ly,1e-6f),0.f),1.f);
    float gx = x01*127.f, gy = y01*127.f;
    int x0 = (int)floorf(gx), y0 = (int)floorf(gy);
    int x1 = min(x0+1,127),  y1 = min(y0+1,127);
    float wx = gx-(float)x0, wy = gy-(float)y0;

    float outAcc = 0.f;

    for(int p=0;p<4;p++){
        int ix = p&1, iy = p>>1;
        int px = ix? x1:x0;
        int py = iy? y1:y0;
        float wgt = (ix? wx : 1.f-wx)*(iy? wy : 1.f-wy);

        for(int m=t;m<288;m+=128){
            int kx=m/12, ky=m-kx*12;
            int kg = kx<12 ? kx : kx+104;
            int mm = (kg*px + ky*py)&127;
            float a = (float)mm*(6.2831853071795864769f/128.f);
            float sv,cv; sincosf(a,&sv,&cv);
            float sc = (ky==0?1.f:2.f)*(1.f/16384.f);
            sPh[m] = make_float2(cv*sc, sv*sc);
        }
        if(t<64) sXv[t] = unpackw(g_xp[((((size_t)(b*64+t))*128+px)<<7)+py]);
        __syncthreads();
        {
            int o = t&63, h = t>>6;
            const float2* op = g_omodes + (size_t)(b*64+o)*288 + h*144;
            const float2* ph = sPh + h*144;
            float acc=0.f;
            #pragma unroll 4
            for(int m=0;m<144;m++){
                float2 z=op[m]; float2 e=ph[m];
                acc += z.x*e.x - z.y*e.y;
            }
            sPart[t]=acc;
        }
        __syncthreads();
        if(t<64){
            float v = sPart[t]+sPart[t+64];
            float a = pwb[t];
            #pragma unroll 4
            for(int c=0;c<64;c++) a += sXv[c]*pw[t*64+c];
            sY3[t] = v + a;
        }
        __syncthreads();
        {
            float a = fc1b[t];
            #pragma unroll 4
            for(int o=0;o<64;o++) a += sY3[o]*fc1w[o*128+t];
            sH[t] = gelu_f(a);
        }
        __syncthreads();
        if(t<3){
            float a = fc2b[t];
            #pragma unroll 4
            for(int f=0;f<128;f++) a += sH[f]*fc2w[f*3+t];
            outAcc += wgt*a;
        }
        __syncthreads();
    }
    if(t<3) out[b*3+t]=outAcc;
}

/* ------------ launch ------------ */
extern "C" void kernel_launch(void* const* d_in, const int* in_sizes, int n_in,
                              void* d_out, int out_size){
    const float* xyt   = (const float*)d_in[0];
    const float* oc    = (const float*)d_in[1];
    const float* ov    = (const float*)d_in[2];
    const float* xg    = (const float*)d_in[3];
    const float* yg    = (const float*)d_in[4];
    const float* fc0w  = (const float*)d_in[5];
    const float* fc0b  = (const float*)d_in[6];
    const float* w1r   = (const float*)d_in[7];
    const float* w1i   = (const float*)d_in[8];
    const float* w2r   = (const float*)d_in[9];
    const float* w2i   = (const float*)d_in[10];
    const float* pww   = (const float*)d_in[11];
    const float* pwb   = (const float*)d_in[12];
    const float* fc1w  = (const float*)d_in[13];
    const float* fc1b  = (const float*)d_in[14];
    const float* fc2w  = (const float*)d_in[15];
    const float* fc2b  = (const float*)d_in[16];
    const int*   nb    = (const int*)d_in[17];
    const int*   siy   = (const int*)d_in[18];
    const int*   six   = (const int*)d_in[19];
    const int*   Lxp   = (const int*)d_in[20];
    const int*   Lyp   = (const int*)d_in[21];
    float* out = (float*)d_out;

    const int SM01 = (64*OPITCH + 128*B2PITCH + 640)*4;
    const int SM5  = (64*APITCH + 96*BPITCH + 128*B2PITCH + 64*OPITCH)*4;
    cudaFuncSetAttribute(k01,    cudaFuncAttributeMaxDynamicSharedMemorySize, SM01);
    cudaFuncSetAttribute(k5_mma, cudaFuncAttributeMaxDynamicSharedMemorySize, SM5);

    k_basis<<<1,256>>>();
    k_zero<<<(BB*SS)/256,256>>>();
    k_scatter<<<1,64>>>(xyt,oc,ov,nb,siy,six);
    k_grid<<<(BB*SS)/256,256>>>();

    k01<<<BB*NXX,256,SM01>>>(xg,yg,fc0w,fc0b);

    for(int L=0;L<4;L++){
        k2_dftx<<<BB*CC,288>>>();
        k3_specmul<<<NMODE*2,256>>>(w1r+(size_t)L*LWSTRIDE, w1i+(size_t)L*LWSTRIDE,
                                    w2r+(size_t)L*LWSTRIDE, w2i+(size_t)L*LWSTRIDE);
        if(L<3){
            k4_invx<<<BB*CC,384>>>();
            k5_mma<<<BB*NXX,256,SM5>>>(pww+(size_t)L*4096, pwb+(size_t)L*64);
        }
    }
    k_final<<<BB,128>>>(xyt, pww+3*4096, pwb+3*64,
                        fc1w, fc1b, fc2w, fc2b, Lxp, Lyp, out);
}